// round 4
// baseline (speedup 1.0000x reference)
#include <cuda_runtime.h>
#include <cuda_fp16.h>
#include <math.h>
#include <cstdint>
#include <cstddef>

#define BATCH 8
#define SEQ   2048
#define EDIM  768
#define DDIM  64
#define MTOT  (BATCH*SEQ)
#define SPLITS 2
#define KVLEN (SEQ/SPLITS)

// fp16 scratch for Q (pre-scaled), K, V
__device__ __half g_q[MTOT*DDIM];
__device__ __half g_k[MTOT*DDIM];
__device__ __half g_v[MTOT*DDIM];
// flash-decoding partials
__device__ float  g_opart[SPLITS*MTOT*DDIM];
__device__ float2 g_ml[SPLITS*MTOT];

// ---------------------------------------------------------------------------
// helpers
// ---------------------------------------------------------------------------
__device__ __forceinline__ float ex2(float x) {
    float y; asm("ex2.approx.ftz.f32 %0, %1;" : "=f"(y) : "f"(x)); return y;
}
__device__ __forceinline__ uint32_t smaddr(const void* p) {
    return (uint32_t)__cvta_generic_to_shared(p);
}
__device__ __forceinline__ void ldsm4(uint32_t& r0, uint32_t& r1, uint32_t& r2,
                                      uint32_t& r3, uint32_t a) {
    asm volatile("ldmatrix.sync.aligned.m8n8.x4.shared.b16 {%0,%1,%2,%3}, [%4];"
                 : "=r"(r0), "=r"(r1), "=r"(r2), "=r"(r3) : "r"(a));
}
__device__ __forceinline__ void ldsm4t(uint32_t& r0, uint32_t& r1, uint32_t& r2,
                                       uint32_t& r3, uint32_t a) {
    asm volatile("ldmatrix.sync.aligned.m8n8.x4.trans.shared.b16 {%0,%1,%2,%3}, [%4];"
                 : "=r"(r0), "=r"(r1), "=r"(r2), "=r"(r3) : "r"(a));
}
__device__ __forceinline__ void mma16(float* d,
                                      uint32_t a0, uint32_t a1, uint32_t a2, uint32_t a3,
                                      uint32_t b0, uint32_t b1) {
    asm volatile(
        "mma.sync.aligned.m16n8k16.row.col.f32.f16.f16.f32 "
        "{%0,%1,%2,%3},{%4,%5,%6,%7},{%8,%9},{%0,%1,%2,%3};"
        : "+f"(d[0]), "+f"(d[1]), "+f"(d[2]), "+f"(d[3])
        : "r"(a0), "r"(a1), "r"(a2), "r"(a3), "r"(b0), "r"(b1));
}
__device__ __forceinline__ void cpasync16(uint32_t dst, const void* src) {
    asm volatile("cp.async.cg.shared.global [%0], [%1], 16;" :: "r"(dst), "l"(src));
}

// ---------------------------------------------------------------------------
// Kernel 1: fused QKV projection, fp16 mma. grid (MTOT/64), block 256 (8 warps).
// Block tile: M=64 rows of X, N=192 (Q|K|V). Warp (wm,wn): rows 16wm..+15,
// cols wn*96..+95 (12 nf). K-tile 32, smem double-buffered (1 sync/tile).
// ---------------------------------------------------------------------------
#define XS_STRIDE 40
#define WS_STRIDE 200
#define XS_ELEMS (64 * XS_STRIDE)
#define WS_ELEMS (32 * WS_STRIDE)

__global__ __launch_bounds__(256) void qkv_mma(
    const float* __restrict__ X,
    const float* __restrict__ Wq, const float* __restrict__ bq,
    const float* __restrict__ Wk, const float* __restrict__ bk,
    const float* __restrict__ Wv, const float* __restrict__ bv)
{
    __shared__ __half Xs[2 * XS_ELEMS];
    __shared__ __half Ws[2 * WS_ELEMS];

    const int r0   = blockIdx.x * 64;
    const int tid  = threadIdx.x;
    const int warp = tid >> 5;
    const int wm   = warp >> 1;       // 0..3
    const int wn   = warp & 1;        // 0..1
    const int lane = tid & 31;
    const int g    = lane >> 2;
    const int tq   = lane & 3;
    const int mat  = lane >> 3;
    const int mr   = lane & 7;

    const float qscale = 0.125f * 1.4426950408889634f;

    float acc[12][4];
    #pragma unroll
    for (int nf = 0; nf < 12; nf++)
        #pragma unroll
        for (int j = 0; j < 4; j++) acc[nf][j] = 0.f;

    // loaders
    const int xr = tid >> 3, xc = (tid & 7) * 4;    // X: 32 rows/pass, 2 passes
    const int wr = tid >> 4, wq4 = (tid & 15) * 4;  // W: 16 rows/pass, 2 passes, 3 mats

    // ldmatrix lane bases (halves)
    const uint32_t a_base0 = smaddr(Xs) +
        ((16*wm + 8*(mat & 1) + mr) * XS_STRIDE + 8*(mat >> 1)) * 2;
    const uint32_t b_base0 = smaddr(Ws) +
        ((8*(mat & 1) + mr) * WS_STRIDE + wn*96 + 8*(mat >> 1)) * 2;

    const float* Wsel[3] = {Wq, Wk, Wv};

    float4 xv[2], wv[6];
    auto ldg_tile = [&](int kt) {
        #pragma unroll
        for (int i = 0; i < 2; i++)
            xv[i] = *reinterpret_cast<const float4*>(
                &X[(size_t)(r0 + xr + 32*i) * EDIM + kt + xc]);
        #pragma unroll
        for (int p = 0; p < 3; p++)
            #pragma unroll
            for (int rh = 0; rh < 2; rh++)
                wv[p*2+rh] = *reinterpret_cast<const float4*>(
                    &Wsel[p][(size_t)(kt + wr + 16*rh) * DDIM + wq4]);
    };
    auto sts_tile = [&](int buf) {
        __half* xb = Xs + buf * XS_ELEMS;
        __half* wb = Ws + buf * WS_ELEMS;
        #pragma unroll
        for (int i = 0; i < 2; i++) {
            __half2* d = reinterpret_cast<__half2*>(&xb[(xr + 32*i) * XS_STRIDE + xc]);
            d[0] = __floats2half2_rn(xv[i].x, xv[i].y);
            d[1] = __floats2half2_rn(xv[i].z, xv[i].w);
        }
        #pragma unroll
        for (int p = 0; p < 3; p++)
            #pragma unroll
            for (int rh = 0; rh < 2; rh++) {
                float4 v = wv[p*2+rh];
                __half2* d = reinterpret_cast<__half2*>(
                    &wb[(wr + 16*rh) * WS_STRIDE + p*64 + wq4]);
                d[0] = __floats2half2_rn(v.x, v.y);
                d[1] = __floats2half2_rn(v.z, v.w);
            }
    };

    ldg_tile(0);
    sts_tile(0);

    const int NT = EDIM / 32;   // 24
    for (int t = 0; t < NT; t++) {
        const int buf = t & 1;
        if (t + 1 < NT) ldg_tile((t + 1) * 32);
        __syncthreads();

        const uint32_t ab = a_base0 + buf * XS_ELEMS * 2;
        const uint32_t bb = b_base0 + buf * WS_ELEMS * 2;
        #pragma unroll
        for (int k16 = 0; k16 < 2; k16++) {
            uint32_t a0, a1, a2, a3;
            ldsm4(a0, a1, a2, a3, ab + (k16*16) * 2);
            #pragma unroll
            for (int nf2 = 0; nf2 < 12; nf2 += 2) {
                uint32_t b0, b1, b2, b3;
                ldsm4t(b0, b1, b2, b3, bb + (k16*16*WS_STRIDE + nf2*8) * 2);
                mma16(acc[nf2],   a0, a1, a2, a3, b0, b1);
                mma16(acc[nf2+1], a0, a1, a2, a3, b2, b3);
            }
        }
        if (t + 1 < NT) sts_tile(buf ^ 1);
    }

    // epilogue: +bias, scale (q only), convert fp16, store
    #pragma unroll
    for (int nf = 0; nf < 12; nf++) {
        int gcol  = wn*96 + nf*8 + 2*tq;
        int which = gcol >> 6;
        int cin   = gcol & 63;
        const float* bp = (which == 0) ? bq : (which == 1) ? bk : bv;
        __half*      op = (which == 0) ? g_q : (which == 1) ? g_k : g_v;
        float sc  = (which == 0) ? qscale : 1.f;
        float bb0 = bp[cin], bb1 = bp[cin + 1];
        int row0 = r0 + 16*wm + g;
        __half2 v0 = __floats2half2_rn((acc[nf][0] + bb0) * sc, (acc[nf][1] + bb1) * sc);
        __half2 v1 = __floats2half2_rn((acc[nf][2] + bb0) * sc, (acc[nf][3] + bb1) * sc);
        *reinterpret_cast<__half2*>(&op[(size_t)row0 * DDIM + cin])     = v0;
        *reinterpret_cast<__half2*>(&op[(size_t)(row0+8) * DDIM + cin]) = v1;
    }
}

// ---------------------------------------------------------------------------
// Kernel 2: flash attention with KV-split. grid (SEQ/64, BATCH, SPLITS),
// block 128 (4 warps). Split z handles keys [z*KVLEN, (z+1)*KVLEN).
// Writes unnormalized partial O + (m,l); merge kernel combines.
// ---------------------------------------------------------------------------
#define KV_STRIDE 72
#define KVBUF (64 * KV_STRIDE)

__global__ __launch_bounds__(128) void attn_mma()
{
    __shared__ __half smkv[4 * KVBUF];  // [K0][V0][K1][V1]

    const int b    = blockIdx.y;
    const int q0   = blockIdx.x * 64;
    const int z    = blockIdx.z;
    const int kt0  = z * KVLEN;
    const int tid  = threadIdx.x;
    const int warp = tid >> 5;
    const int lane = tid & 31;
    const int g    = lane >> 2;
    const int tq   = lane & 3;
    const int mat  = lane >> 3;
    const int mr   = lane & 7;

    // Q fragments (already scaled by 0.125*log2e)
    const __half* qrow = g_q + (size_t)(b*SEQ + q0 + 16*warp + g) * DDIM;
    uint32_t qa[4][4];
    #pragma unroll
    for (int k16 = 0; k16 < 4; k16++) {
        qa[k16][0] = *reinterpret_cast<const uint32_t*>(qrow          + k16*16 + 2*tq);
        qa[k16][1] = *reinterpret_cast<const uint32_t*>(qrow + 8*DDIM + k16*16 + 2*tq);
        qa[k16][2] = *reinterpret_cast<const uint32_t*>(qrow          + k16*16 + 8 + 2*tq);
        qa[k16][3] = *reinterpret_cast<const uint32_t*>(qrow + 8*DDIM + k16*16 + 8 + 2*tq);
    }

    float m0 = -INFINITY, m1 = -INFINITY, l0 = 0.f, l1 = 0.f;
    float o[8][4];
    #pragma unroll
    for (int nf = 0; nf < 8; nf++)
        #pragma unroll
        for (int j = 0; j < 4; j++) o[nf][j] = 0.f;

    const uint32_t kv_base_sm = smaddr(smkv);
    const __half* gk = g_k + (size_t)(b*SEQ) * DDIM;
    const __half* gv = g_v + (size_t)(b*SEQ) * DDIM;

    auto issue_tile = [&](int kt, int buf) {
        uint32_t kdst = kv_base_sm + (2*buf) * KVBUF * 2;
        uint32_t vdst = kdst + KVBUF * 2;
        #pragma unroll
        for (int i = 0; i < 4; i++) {
            int c = tid + 128*i;
            int row = c >> 3, col16 = c & 7;
            uint32_t doff = (row * KV_STRIDE + col16*8) * 2;
            size_t   goff = (size_t)(kt + row) * DDIM + col16*8;
            cpasync16(kdst + doff, gk + goff);
            cpasync16(vdst + doff, gv + goff);
        }
    };

    const uint32_t k_off = ((8*(mat >> 1) + mr) * KV_STRIDE + 8*(mat & 1)) * 2;
    const uint32_t v_off = ((8*(mat & 1) + mr) * KV_STRIDE + 8*(mat >> 1)) * 2;

    issue_tile(kt0, 0);
    asm volatile("cp.async.commit_group;");

    const int NT = KVLEN / 64;    // 16
    for (int it = 0; it < NT; ++it) {
        const int cur = it & 1;
        if (it + 1 < NT) {
            issue_tile(kt0 + (it+1)*64, cur ^ 1);
            asm volatile("cp.async.commit_group;");
            asm volatile("cp.async.wait_group 1;");
        } else {
            asm volatile("cp.async.wait_group 0;");
        }
        __syncthreads();

        const uint32_t ks = kv_base_sm + (2*cur) * KVBUF * 2;
        const uint32_t vs = ks + KVBUF * 2;

        // GEMM1: S = Q K^T
        float s[8][4];
        #pragma unroll
        for (int nf = 0; nf < 8; nf++)
            #pragma unroll
            for (int j = 0; j < 4; j++) s[nf][j] = 0.f;

        #pragma unroll
        for (int k16 = 0; k16 < 4; k16++) {
            #pragma unroll
            for (int nf2 = 0; nf2 < 8; nf2 += 2) {
                uint32_t b0, b1, b2, b3;
                ldsm4(b0, b1, b2, b3, ks + k_off + (nf2*8*KV_STRIDE + k16*16) * 2);
                mma16(s[nf2],   qa[k16][0], qa[k16][1], qa[k16][2], qa[k16][3], b0, b1);
                mma16(s[nf2+1], qa[k16][0], qa[k16][1], qa[k16][2], qa[k16][3], b2, b3);
            }
        }

        // online softmax (base-2)
        float rm0 = -INFINITY, rm1 = -INFINITY;
        #pragma unroll
        for (int nf = 0; nf < 8; nf++) {
            rm0 = fmaxf(rm0, fmaxf(s[nf][0], s[nf][1]));
            rm1 = fmaxf(rm1, fmaxf(s[nf][2], s[nf][3]));
        }
        rm0 = fmaxf(rm0, __shfl_xor_sync(0xffffffffu, rm0, 1));
        rm0 = fmaxf(rm0, __shfl_xor_sync(0xffffffffu, rm0, 2));
        rm1 = fmaxf(rm1, __shfl_xor_sync(0xffffffffu, rm1, 1));
        rm1 = fmaxf(rm1, __shfl_xor_sync(0xffffffffu, rm1, 2));

        float mn0 = fmaxf(m0, rm0), mn1 = fmaxf(m1, rm1);
        float cr0 = ex2(m0 - mn0),  cr1 = ex2(m1 - mn1);
        float rs0 = 0.f, rs1 = 0.f;
        uint32_t ph0[8], ph1[8];

        #pragma unroll
        for (int nf = 0; nf < 8; nf++) {
            float p0 = ex2(s[nf][0] - mn0);
            float p1 = ex2(s[nf][1] - mn0);
            float p2 = ex2(s[nf][2] - mn1);
            float p3 = ex2(s[nf][3] - mn1);
            rs0 += p0 + p1;  rs1 += p2 + p3;
            __half2 h0 = __floats2half2_rn(p0, p1);
            __half2 h1 = __floats2half2_rn(p2, p3);
            ph0[nf] = *reinterpret_cast<uint32_t*>(&h0);
            ph1[nf] = *reinterpret_cast<uint32_t*>(&h1);
            o[nf][0] *= cr0; o[nf][1] *= cr0;
            o[nf][2] *= cr1; o[nf][3] *= cr1;
        }
        rs0 += __shfl_xor_sync(0xffffffffu, rs0, 1);
        rs0 += __shfl_xor_sync(0xffffffffu, rs0, 2);
        rs1 += __shfl_xor_sync(0xffffffffu, rs1, 1);
        rs1 += __shfl_xor_sync(0xffffffffu, rs1, 2);
        l0 = l0 * cr0 + rs0;
        l1 = l1 * cr1 + rs1;
        m0 = mn0; m1 = mn1;

        // GEMM2: O += P V
        #pragma unroll
        for (int k16 = 0; k16 < 4; k16++) {
            uint32_t pa0 = ph0[2*k16],   pa1 = ph1[2*k16];
            uint32_t pa2 = ph0[2*k16+1], pa3 = ph1[2*k16+1];
            #pragma unroll
            for (int nf2 = 0; nf2 < 8; nf2 += 2) {
                uint32_t b0, b1, b2, b3;
                ldsm4t(b0, b1, b2, b3, vs + v_off + (k16*16*KV_STRIDE + nf2*8) * 2);
                mma16(o[nf2],   pa0, pa1, pa2, pa3, b0, b1);
                mma16(o[nf2+1], pa0, pa1, pa2, pa3, b2, b3);
            }
        }
        __syncthreads();
    }

    // epilogue: write unnormalized partials + (m,l)
    const int row_g = b*SEQ + q0 + 16*warp + g;
    float* op = g_opart + ((size_t)z * MTOT + row_g) * DDIM;
    #pragma unroll
    for (int nf = 0; nf < 8; nf++) {
        int c = nf*8 + 2*tq;
        *reinterpret_cast<float2*>(&op[c])          = make_float2(o[nf][0], o[nf][1]);
        *reinterpret_cast<float2*>(&op[8*DDIM + c]) = make_float2(o[nf][2], o[nf][3]);
    }
    if (tq == 0) {
        g_ml[(size_t)z * MTOT + row_g]     = make_float2(m0, l0);
        g_ml[(size_t)z * MTOT + row_g + 8] = make_float2(m1, l1);
    }
}

// ---------------------------------------------------------------------------
// Kernel 3: merge splits.  One float4 per thread.
// ---------------------------------------------------------------------------
__global__ __launch_bounds__(256) void merge_kernel(float* __restrict__ out)
{
    int idx = blockIdx.x * 256 + threadIdx.x;   // 0 .. MTOT*DDIM/4-1
    int row = idx >> 4;
    int c   = (idx & 15) * 4;

    float2 a_ml = g_ml[row];
    float2 b_ml = g_ml[MTOT + row];
    float M  = fmaxf(a_ml.x, b_ml.x);
    float w0 = ex2(a_ml.x - M);
    float w1 = ex2(b_ml.x - M);
    float inv = 1.f / (a_ml.y * w0 + b_ml.y * w1);

    float4 a = *reinterpret_cast<const float4*>(&g_opart[(size_t)row * DDIM + c]);
    float4 bb = *reinterpret_cast<const float4*>(
        &g_opart[(size_t)(MTOT + row) * DDIM + c]);
    float4 r = make_float4((a.x*w0 + bb.x*w1) * inv,
                           (a.y*w0 + bb.y*w1) * inv,
                           (a.z*w0 + bb.z*w1) * inv,
                           (a.w*w0 + bb.w*w1) * inv);
    *reinterpret_cast<float4*>(&out[(size_t)row * DDIM + c]) = r;
}

// ---------------------------------------------------------------------------
extern "C" void kernel_launch(void* const* d_in, const int* in_sizes, int n_in,
                              void* d_out, int out_size)
{
    const float* X  = (const float*)d_in[0];
    const float* Wq = (const float*)d_in[1];
    const float* bq = (const float*)d_in[2];
    const float* Wk = (const float*)d_in[3];
    const float* bk = (const float*)d_in[4];
    const float* Wv = (const float*)d_in[5];
    const float* bv = (const float*)d_in[6];
    float* out = (float*)d_out;

    qkv_mma<<<dim3(MTOT/64), 256>>>(X, Wq, bq, Wk, bk, Wv, bv);
    attn_mma<<<dim3(SEQ/64, BATCH, SPLITS), 128>>>();
    merge_kernel<<<(MTOT*DDIM/4 + 255)/256, 256>>>(out);
}

// round 5
// speedup vs baseline: 1.2983x; 1.2983x over previous
#include <cuda_runtime.h>
#include <cuda_fp16.h>
#include <math.h>
#include <cstdint>
#include <cstddef>

#define BATCH 8
#define SEQ   2048
#define EDIM  768
#define DDIM  64
#define MTOT  (BATCH*SEQ)
#define SPLITS 4
#define KVLEN (SEQ/SPLITS)

// fp16 scratch for Q (pre-scaled), K, V
__device__ __half g_q[MTOT*DDIM];
__device__ __half g_k[MTOT*DDIM];
__device__ __half g_v[MTOT*DDIM];
// flash-decoding partials
__device__ float  g_opart[SPLITS*MTOT*DDIM];
__device__ float2 g_ml[SPLITS*MTOT];

// ---------------------------------------------------------------------------
// helpers
// ---------------------------------------------------------------------------
__device__ __forceinline__ float ex2(float x) {
    float y; asm("ex2.approx.ftz.f32 %0, %1;" : "=f"(y) : "f"(x)); return y;
}
__device__ __forceinline__ uint32_t smaddr(const void* p) {
    return (uint32_t)__cvta_generic_to_shared(p);
}
__device__ __forceinline__ void ldsm4(uint32_t& r0, uint32_t& r1, uint32_t& r2,
                                      uint32_t& r3, uint32_t a) {
    asm volatile("ldmatrix.sync.aligned.m8n8.x4.shared.b16 {%0,%1,%2,%3}, [%4];"
                 : "=r"(r0), "=r"(r1), "=r"(r2), "=r"(r3) : "r"(a));
}
__device__ __forceinline__ void ldsm4t(uint32_t& r0, uint32_t& r1, uint32_t& r2,
                                       uint32_t& r3, uint32_t a) {
    asm volatile("ldmatrix.sync.aligned.m8n8.x4.trans.shared.b16 {%0,%1,%2,%3}, [%4];"
                 : "=r"(r0), "=r"(r1), "=r"(r2), "=r"(r3) : "r"(a));
}
__device__ __forceinline__ void mma16(float* d,
                                      uint32_t a0, uint32_t a1, uint32_t a2, uint32_t a3,
                                      uint32_t b0, uint32_t b1) {
    asm volatile(
        "mma.sync.aligned.m16n8k16.row.col.f32.f16.f16.f32 "
        "{%0,%1,%2,%3},{%4,%5,%6,%7},{%8,%9},{%0,%1,%2,%3};"
        : "+f"(d[0]), "+f"(d[1]), "+f"(d[2]), "+f"(d[3])
        : "r"(a0), "r"(a1), "r"(a2), "r"(a3), "r"(b0), "r"(b1));
}
__device__ __forceinline__ void cpasync16(uint32_t dst, const void* src) {
    asm volatile("cp.async.cg.shared.global [%0], [%1], 16;" :: "r"(dst), "l"(src));
}

// ---------------------------------------------------------------------------
// Kernel 1: fused QKV projection, fp16 mma. grid (MTOT/128), block 512 (16 warps).
// Block tile: M=128, N=192 (Q|K|V). Warp (wm,wn): rows 32wm..+31 (2 m-frags),
// cols wn*48..+47 (6 nf). K-tile 32, smem double-buffered, 1 sync/tile.
// ---------------------------------------------------------------------------
#define XS_STRIDE 40
#define WS_STRIDE 200
#define XS_ELEMS (128 * XS_STRIDE)
#define WS_ELEMS (32 * WS_STRIDE)

__global__ __launch_bounds__(512) void qkv_mma(
    const float* __restrict__ X,
    const float* __restrict__ Wq, const float* __restrict__ bq,
    const float* __restrict__ Wk, const float* __restrict__ bk,
    const float* __restrict__ Wv, const float* __restrict__ bv)
{
    __shared__ __half Xs[2 * XS_ELEMS];   // 20480 B
    __shared__ __half Ws[2 * WS_ELEMS];   // 25600 B

    const int r0   = blockIdx.x * 128;
    const int tid  = threadIdx.x;
    const int warp = tid >> 5;
    const int wm   = warp >> 2;       // 0..3
    const int wn   = warp & 3;        // 0..3
    const int lane = tid & 31;
    const int g    = lane >> 2;
    const int tq   = lane & 3;
    const int mat  = lane >> 3;
    const int mr   = lane & 7;

    const float qscale = 0.125f * 1.4426950408889634f;

    float acc[2][6][4];
    #pragma unroll
    for (int mf = 0; mf < 2; mf++)
        #pragma unroll
        for (int nf = 0; nf < 6; nf++)
            #pragma unroll
            for (int j = 0; j < 4; j++) acc[mf][nf][j] = 0.f;

    // loaders: X 64 rows/pass ×2; W 32 rows, 64 cols per matrix, 3 matrices
    const int xr = tid >> 3, xc = (tid & 7) * 4;
    const int wr = tid >> 4, wq4 = (tid & 15) * 4;

    // ldmatrix lane bases (bytes)
    const uint32_t a_base0 = smaddr(Xs) +
        ((32*wm + 8*(mat & 1) + mr) * XS_STRIDE + 8*(mat >> 1)) * 2;
    const uint32_t b_base0 = smaddr(Ws) +
        ((8*(mat & 1) + mr) * WS_STRIDE + wn*48 + 8*(mat >> 1)) * 2;

    const float* Wsel[3] = {Wq, Wk, Wv};

    float4 xv[2], wv[3];
    auto ldg_tile = [&](int kt) {
        #pragma unroll
        for (int i = 0; i < 2; i++)
            xv[i] = *reinterpret_cast<const float4*>(
                &X[(size_t)(r0 + xr + 64*i) * EDIM + kt + xc]);
        #pragma unroll
        for (int p = 0; p < 3; p++)
            wv[p] = *reinterpret_cast<const float4*>(
                &Wsel[p][(size_t)(kt + wr) * DDIM + wq4]);
    };
    auto sts_tile = [&](int buf) {
        __half* xb = Xs + buf * XS_ELEMS;
        __half* wb = Ws + buf * WS_ELEMS;
        #pragma unroll
        for (int i = 0; i < 2; i++) {
            __half2* d = reinterpret_cast<__half2*>(&xb[(xr + 64*i) * XS_STRIDE + xc]);
            d[0] = __floats2half2_rn(xv[i].x, xv[i].y);
            d[1] = __floats2half2_rn(xv[i].z, xv[i].w);
        }
        #pragma unroll
        for (int p = 0; p < 3; p++) {
            __half2* d = reinterpret_cast<__half2*>(&wb[wr * WS_STRIDE + p*64 + wq4]);
            d[0] = __floats2half2_rn(wv[p].x, wv[p].y);
            d[1] = __floats2half2_rn(wv[p].z, wv[p].w);
        }
    };

    ldg_tile(0);
    sts_tile(0);

    const int NT = EDIM / 32;   // 24
    for (int t = 0; t < NT; t++) {
        const int buf = t & 1;
        if (t + 1 < NT) ldg_tile((t + 1) * 32);
        __syncthreads();

        const uint32_t ab = a_base0 + buf * XS_ELEMS * 2;
        const uint32_t bb = b_base0 + buf * WS_ELEMS * 2;
        #pragma unroll
        for (int k16 = 0; k16 < 2; k16++) {
            uint32_t a[2][4];
            #pragma unroll
            for (int mf = 0; mf < 2; mf++)
                ldsm4(a[mf][0], a[mf][1], a[mf][2], a[mf][3],
                      ab + (mf*16*XS_STRIDE + k16*16) * 2);
            #pragma unroll
            for (int nfp = 0; nfp < 3; nfp++) {
                uint32_t b0, b1, b2, b3;
                ldsm4t(b0, b1, b2, b3, bb + (k16*16*WS_STRIDE + nfp*16) * 2);
                #pragma unroll
                for (int mf = 0; mf < 2; mf++) {
                    mma16(acc[mf][2*nfp],   a[mf][0], a[mf][1], a[mf][2], a[mf][3], b0, b1);
                    mma16(acc[mf][2*nfp+1], a[mf][0], a[mf][1], a[mf][2], a[mf][3], b2, b3);
                }
            }
        }
        if (t + 1 < NT) sts_tile(buf ^ 1);
    }

    // epilogue: +bias, scale (q only), convert fp16, store
    #pragma unroll
    for (int mf = 0; mf < 2; mf++)
        #pragma unroll
        for (int nf = 0; nf < 6; nf++) {
            int gcol  = wn*48 + nf*8 + 2*tq;
            int which = gcol >> 6;
            int cin   = gcol & 63;
            const float* bp = (which == 0) ? bq : (which == 1) ? bk : bv;
            __half*      op = (which == 0) ? g_q : (which == 1) ? g_k : g_v;
            float sc  = (which == 0) ? qscale : 1.f;
            float bb0 = bp[cin], bb1 = bp[cin + 1];
            int row0 = r0 + 32*wm + 16*mf + g;
            __half2 v0 = __floats2half2_rn((acc[mf][nf][0] + bb0) * sc,
                                           (acc[mf][nf][1] + bb1) * sc);
            __half2 v1 = __floats2half2_rn((acc[mf][nf][2] + bb0) * sc,
                                           (acc[mf][nf][3] + bb1) * sc);
            *reinterpret_cast<__half2*>(&op[(size_t)row0 * DDIM + cin])     = v0;
            *reinterpret_cast<__half2*>(&op[(size_t)(row0+8) * DDIM + cin]) = v1;
        }
}

// ---------------------------------------------------------------------------
// Kernel 2: flash attention with KV-split. grid (SEQ/64, BATCH, SPLITS),
// block 128 (4 warps). Split z handles keys [z*KVLEN, (z+1)*KVLEN).
// ---------------------------------------------------------------------------
#define KV_STRIDE 72
#define KVBUF (64 * KV_STRIDE)

__global__ __launch_bounds__(128) void attn_mma()
{
    __shared__ __half smkv[4 * KVBUF];  // [K0][V0][K1][V1]

    const int b    = blockIdx.y;
    const int q0   = blockIdx.x * 64;
    const int z    = blockIdx.z;
    const int kt0  = z * KVLEN;
    const int tid  = threadIdx.x;
    const int warp = tid >> 5;
    const int lane = tid & 31;
    const int g    = lane >> 2;
    const int tq   = lane & 3;
    const int mat  = lane >> 3;
    const int mr   = lane & 7;

    const __half* qrow = g_q + (size_t)(b*SEQ + q0 + 16*warp + g) * DDIM;
    uint32_t qa[4][4];
    #pragma unroll
    for (int k16 = 0; k16 < 4; k16++) {
        qa[k16][0] = *reinterpret_cast<const uint32_t*>(qrow          + k16*16 + 2*tq);
        qa[k16][1] = *reinterpret_cast<const uint32_t*>(qrow + 8*DDIM + k16*16 + 2*tq);
        qa[k16][2] = *reinterpret_cast<const uint32_t*>(qrow          + k16*16 + 8 + 2*tq);
        qa[k16][3] = *reinterpret_cast<const uint32_t*>(qrow + 8*DDIM + k16*16 + 8 + 2*tq);
    }

    float m0 = -INFINITY, m1 = -INFINITY, l0 = 0.f, l1 = 0.f;
    float o[8][4];
    #pragma unroll
    for (int nf = 0; nf < 8; nf++)
        #pragma unroll
        for (int j = 0; j < 4; j++) o[nf][j] = 0.f;

    const uint32_t kv_base_sm = smaddr(smkv);
    const __half* gk = g_k + (size_t)(b*SEQ) * DDIM;
    const __half* gv = g_v + (size_t)(b*SEQ) * DDIM;

    auto issue_tile = [&](int kt, int buf) {
        uint32_t kdst = kv_base_sm + (2*buf) * KVBUF * 2;
        uint32_t vdst = kdst + KVBUF * 2;
        #pragma unroll
        for (int i = 0; i < 4; i++) {
            int c = tid + 128*i;
            int row = c >> 3, col16 = c & 7;
            uint32_t doff = (row * KV_STRIDE + col16*8) * 2;
            size_t   goff = (size_t)(kt + row) * DDIM + col16*8;
            cpasync16(kdst + doff, gk + goff);
            cpasync16(vdst + doff, gv + goff);
        }
    };

    const uint32_t k_off = ((8*(mat >> 1) + mr) * KV_STRIDE + 8*(mat & 1)) * 2;
    const uint32_t v_off = ((8*(mat & 1) + mr) * KV_STRIDE + 8*(mat >> 1)) * 2;

    issue_tile(kt0, 0);
    asm volatile("cp.async.commit_group;");

    const int NT = KVLEN / 64;    // 8
    for (int it = 0; it < NT; ++it) {
        const int cur = it & 1;
        if (it + 1 < NT) {
            issue_tile(kt0 + (it+1)*64, cur ^ 1);
            asm volatile("cp.async.commit_group;");
            asm volatile("cp.async.wait_group 1;");
        } else {
            asm volatile("cp.async.wait_group 0;");
        }
        __syncthreads();

        const uint32_t ks = kv_base_sm + (2*cur) * KVBUF * 2;
        const uint32_t vs = ks + KVBUF * 2;

        // GEMM1: S = Q K^T
        float s[8][4];
        #pragma unroll
        for (int nf = 0; nf < 8; nf++)
            #pragma unroll
            for (int j = 0; j < 4; j++) s[nf][j] = 0.f;

        #pragma unroll
        for (int k16 = 0; k16 < 4; k16++) {
            #pragma unroll
            for (int nf2 = 0; nf2 < 8; nf2 += 2) {
                uint32_t b0, b1, b2, b3;
                ldsm4(b0, b1, b2, b3, ks + k_off + (nf2*8*KV_STRIDE + k16*16) * 2);
                mma16(s[nf2],   qa[k16][0], qa[k16][1], qa[k16][2], qa[k16][3], b0, b1);
                mma16(s[nf2+1], qa[k16][0], qa[k16][1], qa[k16][2], qa[k16][3], b2, b3);
            }
        }

        // online softmax (base-2)
        float rm0 = -INFINITY, rm1 = -INFINITY;
        #pragma unroll
        for (int nf = 0; nf < 8; nf++) {
            rm0 = fmaxf(rm0, fmaxf(s[nf][0], s[nf][1]));
            rm1 = fmaxf(rm1, fmaxf(s[nf][2], s[nf][3]));
        }
        rm0 = fmaxf(rm0, __shfl_xor_sync(0xffffffffu, rm0, 1));
        rm0 = fmaxf(rm0, __shfl_xor_sync(0xffffffffu, rm0, 2));
        rm1 = fmaxf(rm1, __shfl_xor_sync(0xffffffffu, rm1, 1));
        rm1 = fmaxf(rm1, __shfl_xor_sync(0xffffffffu, rm1, 2));

        float mn0 = fmaxf(m0, rm0), mn1 = fmaxf(m1, rm1);
        float cr0 = ex2(m0 - mn0),  cr1 = ex2(m1 - mn1);
        float rs0 = 0.f, rs1 = 0.f;
        uint32_t ph0[8], ph1[8];

        #pragma unroll
        for (int nf = 0; nf < 8; nf++) {
            float p0 = ex2(s[nf][0] - mn0);
            float p1 = ex2(s[nf][1] - mn0);
            float p2 = ex2(s[nf][2] - mn1);
            float p3 = ex2(s[nf][3] - mn1);
            rs0 += p0 + p1;  rs1 += p2 + p3;
            __half2 h0 = __floats2half2_rn(p0, p1);
            __half2 h1 = __floats2half2_rn(p2, p3);
            ph0[nf] = *reinterpret_cast<uint32_t*>(&h0);
            ph1[nf] = *reinterpret_cast<uint32_t*>(&h1);
            o[nf][0] *= cr0; o[nf][1] *= cr0;
            o[nf][2] *= cr1; o[nf][3] *= cr1;
        }
        rs0 += __shfl_xor_sync(0xffffffffu, rs0, 1);
        rs0 += __shfl_xor_sync(0xffffffffu, rs0, 2);
        rs1 += __shfl_xor_sync(0xffffffffu, rs1, 1);
        rs1 += __shfl_xor_sync(0xffffffffu, rs1, 2);
        l0 = l0 * cr0 + rs0;
        l1 = l1 * cr1 + rs1;
        m0 = mn0; m1 = mn1;

        // GEMM2: O += P V
        #pragma unroll
        for (int k16 = 0; k16 < 4; k16++) {
            uint32_t pa0 = ph0[2*k16],   pa1 = ph1[2*k16];
            uint32_t pa2 = ph0[2*k16+1], pa3 = ph1[2*k16+1];
            #pragma unroll
            for (int nf2 = 0; nf2 < 8; nf2 += 2) {
                uint32_t b0, b1, b2, b3;
                ldsm4t(b0, b1, b2, b3, vs + v_off + (k16*16*KV_STRIDE + nf2*8) * 2);
                mma16(o[nf2],   pa0, pa1, pa2, pa3, b0, b1);
                mma16(o[nf2+1], pa0, pa1, pa2, pa3, b2, b3);
            }
        }
        __syncthreads();
    }

    // epilogue: write unnormalized partials + (m,l)
    const int row_g = b*SEQ + q0 + 16*warp + g;
    float* op = g_opart + ((size_t)z * MTOT + row_g) * DDIM;
    #pragma unroll
    for (int nf = 0; nf < 8; nf++) {
        int c = nf*8 + 2*tq;
        *reinterpret_cast<float2*>(&op[c])          = make_float2(o[nf][0], o[nf][1]);
        *reinterpret_cast<float2*>(&op[8*DDIM + c]) = make_float2(o[nf][2], o[nf][3]);
    }
    if (tq == 0) {
        g_ml[(size_t)z * MTOT + row_g]     = make_float2(m0, l0);
        g_ml[(size_t)z * MTOT + row_g + 8] = make_float2(m1, l1);
    }
}

// ---------------------------------------------------------------------------
// Kernel 3: merge splits.  One float4 per thread.
// ---------------------------------------------------------------------------
__global__ __launch_bounds__(256) void merge_kernel(float* __restrict__ out)
{
    int idx = blockIdx.x * 256 + threadIdx.x;   // 0 .. MTOT*16-1
    int row = idx >> 4;
    int c   = (idx & 15) * 4;

    float2 ml[SPLITS];
    float M = -INFINITY;
    #pragma unroll
    for (int s = 0; s < SPLITS; s++) {
        ml[s] = g_ml[(size_t)s * MTOT + row];
        M = fmaxf(M, ml[s].x);
    }
    float w[SPLITS];
    float denom = 0.f;
    #pragma unroll
    for (int s = 0; s < SPLITS; s++) {
        w[s] = ex2(ml[s].x - M);
        denom += ml[s].y * w[s];
    }
    float inv = 1.f / denom;

    float4 r = make_float4(0.f, 0.f, 0.f, 0.f);
    #pragma unroll
    for (int s = 0; s < SPLITS; s++) {
        float4 a = *reinterpret_cast<const float4*>(
            &g_opart[((size_t)s * MTOT + row) * DDIM + c]);
        r.x += a.x * w[s]; r.y += a.y * w[s];
        r.z += a.z * w[s]; r.w += a.w * w[s];
    }
    r.x *= inv; r.y *= inv; r.z *= inv; r.w *= inv;
    *reinterpret_cast<float4*>(&out[(size_t)row * DDIM + c]) = r;
}

// ---------------------------------------------------------------------------
extern "C" void kernel_launch(void* const* d_in, const int* in_sizes, int n_in,
                              void* d_out, int out_size)
{
    const float* X  = (const float*)d_in[0];
    const float* Wq = (const float*)d_in[1];
    const float* bq = (const float*)d_in[2];
    const float* Wk = (const float*)d_in[3];
    const float* bk = (const float*)d_in[4];
    const float* Wv = (const float*)d_in[5];
    const float* bv = (const float*)d_in[6];
    float* out = (float*)d_out;

    qkv_mma<<<dim3(MTOT/128), 512>>>(X, Wq, bq, Wk, bk, Wv, bv);
    attn_mma<<<dim3(SEQ/64, BATCH, SPLITS), 128>>>();
    merge_kernel<<<(MTOT*16 + 255)/256, 256>>>(out);
}

// round 6
// speedup vs baseline: 1.3801x; 1.0630x over previous
#include <cuda_runtime.h>
#include <cuda_fp16.h>
#include <math.h>
#include <cstdint>
#include <cstddef>

#define BATCH 8
#define SEQ   2048
#define EDIM  768
#define DDIM  64
#define MTOT  (BATCH*SEQ)
#define SPLITS 2
#define KVLEN (SEQ/SPLITS)

// fp16 scratch for Q (pre-scaled), K, V
__device__ __half g_q[MTOT*DDIM];
__device__ __half g_k[MTOT*DDIM];
__device__ __half g_v[MTOT*DDIM];
// flash-decoding partials
__device__ float  g_opart[SPLITS*MTOT*DDIM];
__device__ float2 g_ml[SPLITS*MTOT];

// ---------------------------------------------------------------------------
// helpers
// ---------------------------------------------------------------------------
__device__ __forceinline__ float ex2(float x) {
    float y; asm("ex2.approx.ftz.f32 %0, %1;" : "=f"(y) : "f"(x)); return y;
}
__device__ __forceinline__ uint32_t smaddr(const void* p) {
    return (uint32_t)__cvta_generic_to_shared(p);
}
__device__ __forceinline__ void ldsm4(uint32_t& r0, uint32_t& r1, uint32_t& r2,
                                      uint32_t& r3, uint32_t a) {
    asm volatile("ldmatrix.sync.aligned.m8n8.x4.shared.b16 {%0,%1,%2,%3}, [%4];"
                 : "=r"(r0), "=r"(r1), "=r"(r2), "=r"(r3) : "r"(a));
}
__device__ __forceinline__ void ldsm4t(uint32_t& r0, uint32_t& r1, uint32_t& r2,
                                       uint32_t& r3, uint32_t a) {
    asm volatile("ldmatrix.sync.aligned.m8n8.x4.trans.shared.b16 {%0,%1,%2,%3}, [%4];"
                 : "=r"(r0), "=r"(r1), "=r"(r2), "=r"(r3) : "r"(a));
}
__device__ __forceinline__ void mma16(float* d,
                                      uint32_t a0, uint32_t a1, uint32_t a2, uint32_t a3,
                                      uint32_t b0, uint32_t b1) {
    asm volatile(
        "mma.sync.aligned.m16n8k16.row.col.f32.f16.f16.f32 "
        "{%0,%1,%2,%3},{%4,%5,%6,%7},{%8,%9},{%0,%1,%2,%3};"
        : "+f"(d[0]), "+f"(d[1]), "+f"(d[2]), "+f"(d[3])
        : "r"(a0), "r"(a1), "r"(a2), "r"(a3), "r"(b0), "r"(b1));
}
__device__ __forceinline__ void cpasync16(uint32_t dst, const void* src) {
    asm volatile("cp.async.cg.shared.global [%0], [%1], 16;" :: "r"(dst), "l"(src));
}

// ---------------------------------------------------------------------------
// Kernel 1: fused QKV projection, fp16 mma. grid (MTOT/128), block 512 (16 warps).
// Block tile: M=128, N=192 (Q|K|V). Warp (wm,wn): rows 32wm..+31 (2 m-frags),
// cols wn*48..+47 (6 nf). K-tile 64, smem double-buffered, 1 sync/tile.
// ---------------------------------------------------------------------------
#define XS_STRIDE 72
#define WS_STRIDE 200
#define XS_ELEMS (128 * XS_STRIDE)
#define WS_ELEMS (64 * WS_STRIDE)
#define QKV_SMEM ((2*XS_ELEMS + 2*WS_ELEMS) * 2)   // 88064 B

__global__ __launch_bounds__(512) void qkv_mma(
    const float* __restrict__ X,
    const float* __restrict__ Wq, const float* __restrict__ bq,
    const float* __restrict__ Wk, const float* __restrict__ bk,
    const float* __restrict__ Wv, const float* __restrict__ bv)
{
    extern __shared__ __half smq[];
    __half* Xs = smq;                      // 2 bufs of [128][72]
    __half* Ws = smq + 2*XS_ELEMS;         // 2 bufs of [64][200]

    const int r0   = blockIdx.x * 128;
    const int tid  = threadIdx.x;
    const int warp = tid >> 5;
    const int wm   = warp >> 2;       // 0..3
    const int wn   = warp & 3;        // 0..3
    const int lane = tid & 31;
    const int g    = lane >> 2;
    const int tq   = lane & 3;
    const int mat  = lane >> 3;
    const int mr   = lane & 7;

    const float qscale = 0.125f * 1.4426950408889634f;

    float acc[2][6][4];
    #pragma unroll
    for (int mf = 0; mf < 2; mf++)
        #pragma unroll
        for (int nf = 0; nf < 6; nf++)
            #pragma unroll
            for (int j = 0; j < 4; j++) acc[mf][nf][j] = 0.f;

    // loaders: X 32 rows/pass ×4 (128 rows × 64 cols); W 32 rows/pass ×2, 3 mats
    const int xr = tid >> 4, xc = (tid & 15) * 4;
    const int wr = tid >> 4, wq4 = (tid & 15) * 4;

    // ldmatrix lane bases (bytes)
    const uint32_t a_base0 = smaddr(Xs) +
        ((32*wm + 8*(mat & 1) + mr) * XS_STRIDE + 8*(mat >> 1)) * 2;
    const uint32_t b_base0 = smaddr(Ws) +
        ((8*(mat & 1) + mr) * WS_STRIDE + wn*48 + 8*(mat >> 1)) * 2;

    const float* Wsel[3] = {Wq, Wk, Wv};

    float4 xv[4], wv[6];
    auto ldg_tile = [&](int kt) {
        #pragma unroll
        for (int i = 0; i < 4; i++)
            xv[i] = *reinterpret_cast<const float4*>(
                &X[(size_t)(r0 + xr + 32*i) * EDIM + kt + xc]);
        #pragma unroll
        for (int p = 0; p < 3; p++)
            #pragma unroll
            for (int i = 0; i < 2; i++)
                wv[p*2+i] = *reinterpret_cast<const float4*>(
                    &Wsel[p][(size_t)(kt + wr + 32*i) * DDIM + wq4]);
    };
    auto sts_tile = [&](int buf) {
        __half* xb = Xs + buf * XS_ELEMS;
        __half* wb = Ws + buf * WS_ELEMS;
        #pragma unroll
        for (int i = 0; i < 4; i++) {
            __half2* d = reinterpret_cast<__half2*>(&xb[(xr + 32*i) * XS_STRIDE + xc]);
            d[0] = __floats2half2_rn(xv[i].x, xv[i].y);
            d[1] = __floats2half2_rn(xv[i].z, xv[i].w);
        }
        #pragma unroll
        for (int p = 0; p < 3; p++)
            #pragma unroll
            for (int i = 0; i < 2; i++) {
                float4 v = wv[p*2+i];
                __half2* d = reinterpret_cast<__half2*>(
                    &wb[(wr + 32*i) * WS_STRIDE + p*64 + wq4]);
                d[0] = __floats2half2_rn(v.x, v.y);
                d[1] = __floats2half2_rn(v.z, v.w);
            }
    };

    ldg_tile(0);
    sts_tile(0);

    const int NT = EDIM / 64;   // 12
    for (int t = 0; t < NT; t++) {
        const int buf = t & 1;
        if (t + 1 < NT) ldg_tile((t + 1) * 64);
        __syncthreads();

        const uint32_t ab = a_base0 + buf * XS_ELEMS * 2;
        const uint32_t bb = b_base0 + buf * WS_ELEMS * 2;
        #pragma unroll
        for (int k16 = 0; k16 < 4; k16++) {
            uint32_t a[2][4];
            #pragma unroll
            for (int mf = 0; mf < 2; mf++)
                ldsm4(a[mf][0], a[mf][1], a[mf][2], a[mf][3],
                      ab + (mf*16*XS_STRIDE + k16*16) * 2);
            #pragma unroll
            for (int nfp = 0; nfp < 3; nfp++) {
                uint32_t b0, b1, b2, b3;
                ldsm4t(b0, b1, b2, b3, bb + (k16*16*WS_STRIDE + nfp*16) * 2);
                #pragma unroll
                for (int mf = 0; mf < 2; mf++) {
                    mma16(acc[mf][2*nfp],   a[mf][0], a[mf][1], a[mf][2], a[mf][3], b0, b1);
                    mma16(acc[mf][2*nfp+1], a[mf][0], a[mf][1], a[mf][2], a[mf][3], b2, b3);
                }
            }
        }
        if (t + 1 < NT) sts_tile(buf ^ 1);
    }

    // epilogue: +bias, scale (q only), convert fp16, store
    #pragma unroll
    for (int mf = 0; mf < 2; mf++)
        #pragma unroll
        for (int nf = 0; nf < 6; nf++) {
            int gcol  = wn*48 + nf*8 + 2*tq;
            int which = gcol >> 6;
            int cin   = gcol & 63;
            const float* bp = (which == 0) ? bq : (which == 1) ? bk : bv;
            __half*      op = (which == 0) ? g_q : (which == 1) ? g_k : g_v;
            float sc  = (which == 0) ? qscale : 1.f;
            float bb0 = bp[cin], bb1 = bp[cin + 1];
            int row0 = r0 + 32*wm + 16*mf + g;
            __half2 v0 = __floats2half2_rn((acc[mf][nf][0] + bb0) * sc,
                                           (acc[mf][nf][1] + bb1) * sc);
            __half2 v1 = __floats2half2_rn((acc[mf][nf][2] + bb0) * sc,
                                           (acc[mf][nf][3] + bb1) * sc);
            *reinterpret_cast<__half2*>(&op[(size_t)row0 * DDIM + cin])     = v0;
            *reinterpret_cast<__half2*>(&op[(size_t)(row0+8) * DDIM + cin]) = v1;
        }
}

// ---------------------------------------------------------------------------
// Kernel 2: flash attention. grid (SEQ/128, BATCH, SPLITS), block 256 (8 warps).
// Q-tile 128 (16 rows/warp). 3-stage cp.async ring on K/V tiles of 64.
// ---------------------------------------------------------------------------
#define KV_STRIDE 72
#define KVBUF (64 * KV_STRIDE)                 // halves per K (or V) buffer
#define ATTN_SMEM (3 * 2 * KVBUF * 2)          // 55296 B

__global__ __launch_bounds__(256, 2) void attn_mma()
{
    extern __shared__ __half smkv[];           // 3 stages of [K][V]

    const int b    = blockIdx.y;
    const int q0   = blockIdx.x * 128;
    const int z    = blockIdx.z;
    const int kt0  = z * KVLEN;
    const int tid  = threadIdx.x;
    const int warp = tid >> 5;                 // 0..7
    const int lane = tid & 31;
    const int g    = lane >> 2;
    const int tq   = lane & 3;
    const int mat  = lane >> 3;
    const int mr   = lane & 7;

    // Q fragments (already scaled by 0.125*log2e)
    const __half* qrow = g_q + (size_t)(b*SEQ + q0 + 16*warp + g) * DDIM;
    uint32_t qa[4][4];
    #pragma unroll
    for (int k16 = 0; k16 < 4; k16++) {
        qa[k16][0] = *reinterpret_cast<const uint32_t*>(qrow          + k16*16 + 2*tq);
        qa[k16][1] = *reinterpret_cast<const uint32_t*>(qrow + 8*DDIM + k16*16 + 2*tq);
        qa[k16][2] = *reinterpret_cast<const uint32_t*>(qrow          + k16*16 + 8 + 2*tq);
        qa[k16][3] = *reinterpret_cast<const uint32_t*>(qrow + 8*DDIM + k16*16 + 8 + 2*tq);
    }

    float m0 = -INFINITY, m1 = -INFINITY, l0 = 0.f, l1 = 0.f;
    float o[8][4];
    #pragma unroll
    for (int nf = 0; nf < 8; nf++)
        #pragma unroll
        for (int j = 0; j < 4; j++) o[nf][j] = 0.f;

    const uint32_t kv_base_sm = smaddr(smkv);
    const __half* gk = g_k + (size_t)(b*SEQ) * DDIM;
    const __half* gv = g_v + (size_t)(b*SEQ) * DDIM;

    // loader: 2 chunks of 16B per thread per array (64 rows x 64 cols fp16)
    auto issue_tile = [&](int kt, int buf) {
        uint32_t kdst = kv_base_sm + buf * (2*KVBUF*2);
        uint32_t vdst = kdst + KVBUF*2;
        #pragma unroll
        for (int i = 0; i < 2; i++) {
            int c = tid + 256*i;
            int row = c >> 3, col16 = c & 7;
            uint32_t doff = (row * KV_STRIDE + col16*8) * 2;
            size_t   goff = (size_t)(kt + row) * DDIM + col16*8;
            cpasync16(kdst + doff, gk + goff);
            cpasync16(vdst + doff, gv + goff);
        }
    };

    const uint32_t k_off = ((8*(mat >> 1) + mr) * KV_STRIDE + 8*(mat & 1)) * 2;
    const uint32_t v_off = ((8*(mat & 1) + mr) * KV_STRIDE + 8*(mat >> 1)) * 2;

    const int NT = KVLEN / 64;    // 16
    issue_tile(kt0, 0);
    asm volatile("cp.async.commit_group;");
    issue_tile(kt0 + 64, 1);
    asm volatile("cp.async.commit_group;");

    int cur = 0, nxt = 2;   // nxt = buffer for tile it+2
    for (int it = 0; it < NT; ++it) {
        if (it + 2 < NT) {
            issue_tile(kt0 + (it+2)*64, nxt);
            asm volatile("cp.async.commit_group;");
            asm volatile("cp.async.wait_group 2;");
        } else if (it + 1 < NT) {
            asm volatile("cp.async.wait_group 1;");
        } else {
            asm volatile("cp.async.wait_group 0;");
        }
        __syncthreads();

        const uint32_t ks = kv_base_sm + cur * (2*KVBUF*2);
        const uint32_t vs = ks + KVBUF*2;

        // GEMM1: S = Q K^T
        float s[8][4];
        #pragma unroll
        for (int nf = 0; nf < 8; nf++)
            #pragma unroll
            for (int j = 0; j < 4; j++) s[nf][j] = 0.f;

        #pragma unroll
        for (int k16 = 0; k16 < 4; k16++) {
            #pragma unroll
            for (int nf2 = 0; nf2 < 8; nf2 += 2) {
                uint32_t b0, b1, b2, b3;
                ldsm4(b0, b1, b2, b3, ks + k_off + (nf2*8*KV_STRIDE + k16*16) * 2);
                mma16(s[nf2],   qa[k16][0], qa[k16][1], qa[k16][2], qa[k16][3], b0, b1);
                mma16(s[nf2+1], qa[k16][0], qa[k16][1], qa[k16][2], qa[k16][3], b2, b3);
            }
        }

        // online softmax (base-2)
        float rm0 = -INFINITY, rm1 = -INFINITY;
        #pragma unroll
        for (int nf = 0; nf < 8; nf++) {
            rm0 = fmaxf(rm0, fmaxf(s[nf][0], s[nf][1]));
            rm1 = fmaxf(rm1, fmaxf(s[nf][2], s[nf][3]));
        }
        rm0 = fmaxf(rm0, __shfl_xor_sync(0xffffffffu, rm0, 1));
        rm0 = fmaxf(rm0, __shfl_xor_sync(0xffffffffu, rm0, 2));
        rm1 = fmaxf(rm1, __shfl_xor_sync(0xffffffffu, rm1, 1));
        rm1 = fmaxf(rm1, __shfl_xor_sync(0xffffffffu, rm1, 2));

        float mn0 = fmaxf(m0, rm0), mn1 = fmaxf(m1, rm1);
        float cr0 = ex2(m0 - mn0),  cr1 = ex2(m1 - mn1);
        float rs0 = 0.f, rs1 = 0.f;
        uint32_t ph0[8], ph1[8];

        #pragma unroll
        for (int nf = 0; nf < 8; nf++) {
            float p0 = ex2(s[nf][0] - mn0);
            float p1 = ex2(s[nf][1] - mn0);
            float p2 = ex2(s[nf][2] - mn1);
            float p3 = ex2(s[nf][3] - mn1);
            rs0 += p0 + p1;  rs1 += p2 + p3;
            __half2 h0 = __floats2half2_rn(p0, p1);
            __half2 h1 = __floats2half2_rn(p2, p3);
            ph0[nf] = *reinterpret_cast<uint32_t*>(&h0);
            ph1[nf] = *reinterpret_cast<uint32_t*>(&h1);
            o[nf][0] *= cr0; o[nf][1] *= cr0;
            o[nf][2] *= cr1; o[nf][3] *= cr1;
        }
        rs0 += __shfl_xor_sync(0xffffffffu, rs0, 1);
        rs0 += __shfl_xor_sync(0xffffffffu, rs0, 2);
        rs1 += __shfl_xor_sync(0xffffffffu, rs1, 1);
        rs1 += __shfl_xor_sync(0xffffffffu, rs1, 2);
        l0 = l0 * cr0 + rs0;
        l1 = l1 * cr1 + rs1;
        m0 = mn0; m1 = mn1;

        // GEMM2: O += P V
        #pragma unroll
        for (int k16 = 0; k16 < 4; k16++) {
            uint32_t pa0 = ph0[2*k16],   pa1 = ph1[2*k16];
            uint32_t pa2 = ph0[2*k16+1], pa3 = ph1[2*k16+1];
            #pragma unroll
            for (int nf2 = 0; nf2 < 8; nf2 += 2) {
                uint32_t b0, b1, b2, b3;
                ldsm4t(b0, b1, b2, b3, vs + v_off + (k16*16*KV_STRIDE + nf2*8) * 2);
                mma16(o[nf2],   pa0, pa1, pa2, pa3, b0, b1);
                mma16(o[nf2+1], pa0, pa1, pa2, pa3, b2, b3);
            }
        }
        __syncthreads();   // all warps done with buffer `cur` before it is refilled

        cur = (cur == 2) ? 0 : cur + 1;
        nxt = (nxt == 2) ? 0 : nxt + 1;
    }

    // epilogue: write unnormalized partials + (m,l)
    const int row_g = b*SEQ + q0 + 16*warp + g;
    float* op = g_opart + ((size_t)z * MTOT + row_g) * DDIM;
    #pragma unroll
    for (int nf = 0; nf < 8; nf++) {
        int c = nf*8 + 2*tq;
        *reinterpret_cast<float2*>(&op[c])          = make_float2(o[nf][0], o[nf][1]);
        *reinterpret_cast<float2*>(&op[8*DDIM + c]) = make_float2(o[nf][2], o[nf][3]);
    }
    if (tq == 0) {
        g_ml[(size_t)z * MTOT + row_g]     = make_float2(m0, l0);
        g_ml[(size_t)z * MTOT + row_g + 8] = make_float2(m1, l1);
    }
}

// ---------------------------------------------------------------------------
// Kernel 3: merge splits.  One float4 per thread.
// ---------------------------------------------------------------------------
__global__ __launch_bounds__(256) void merge_kernel(float* __restrict__ out)
{
    int idx = blockIdx.x * 256 + threadIdx.x;   // 0 .. MTOT*16-1
    int row = idx >> 4;
    int c   = (idx & 15) * 4;

    float2 a_ml = g_ml[row];
    float2 b_ml = g_ml[MTOT + row];
    float M  = fmaxf(a_ml.x, b_ml.x);
    float w0 = ex2(a_ml.x - M);
    float w1 = ex2(b_ml.x - M);
    float inv = 1.f / (a_ml.y * w0 + b_ml.y * w1);

    float4 a = *reinterpret_cast<const float4*>(&g_opart[(size_t)row * DDIM + c]);
    float4 bb = *reinterpret_cast<const float4*>(
        &g_opart[(size_t)(MTOT + row) * DDIM + c]);
    float4 r = make_float4((a.x*w0 + bb.x*w1) * inv,
                           (a.y*w0 + bb.y*w1) * inv,
                           (a.z*w0 + bb.z*w1) * inv,
                           (a.w*w0 + bb.w*w1) * inv);
    *reinterpret_cast<float4*>(&out[(size_t)row * DDIM + c]) = r;
}

// ---------------------------------------------------------------------------
extern "C" void kernel_launch(void* const* d_in, const int* in_sizes, int n_in,
                              void* d_out, int out_size)
{
    const float* X  = (const float*)d_in[0];
    const float* Wq = (const float*)d_in[1];
    const float* bq = (const float*)d_in[2];
    const float* Wk = (const float*)d_in[3];
    const float* bk = (const float*)d_in[4];
    const float* Wv = (const float*)d_in[5];
    const float* bv = (const float*)d_in[6];
    float* out = (float*)d_out;

    cudaFuncSetAttribute(qkv_mma,
                         cudaFuncAttributeMaxDynamicSharedMemorySize, QKV_SMEM);
    cudaFuncSetAttribute(attn_mma,
                         cudaFuncAttributeMaxDynamicSharedMemorySize, ATTN_SMEM);

    qkv_mma<<<dim3(MTOT/128), 512, QKV_SMEM>>>(X, Wq, bq, Wk, bk, Wv, bv);
    attn_mma<<<dim3(SEQ/128, BATCH, SPLITS), 256, ATTN_SMEM>>>();
    merge_kernel<<<(MTOT*16 + 255)/256, 256>>>(out);
}